// round 10
// baseline (speedup 1.0000x reference)
#include <cuda_runtime.h>
#include <cstdint>

#define L_SEQ  50
#define BATCH  256
#define DIN    256
#define LAT    512
#define HODE   1024
#define HID    1024
#define DSTRIDE 257
#define JC     3072
#define OUT2_OFF (L_SEQ*BATCH*LAT)
#define NB     256

// ---- persistent scratch ----
__device__ float g_S0[BATCH*LAT];
__device__ float g_S1[BATCH*LAT];
__device__ float g_Y [BATCH*LAT];
__device__ float g_P [4][BATCH*HODE];     // mlp1 split-K partials
__device__ float g_Q [8][BATCH*LAT];      // mlp2 split-K partials
__device__ float g_Gp[3][BATCH*3072];     // gru partials per K-slice, gate-major
__device__ float g_W1c [LAT*HODE];        // tf32-rounded weights
__device__ float g_W2c [HODE*LAT];
__device__ float g_WihTc[DIN*JC];
__device__ float g_WhhTc[HID*JC];

// ---- software grid barrier ----
__device__ unsigned g_cnt = 0;
__device__ volatile unsigned g_sense = 0;

__device__ __forceinline__ void gridbar(){
    __syncthreads();
    if (threadIdx.x == 0){
        __threadfence();
        unsigned s = g_sense;
        if (atomicAdd(&g_cnt, 1u) == NB-1u){
            g_cnt = 0u;
            __threadfence();
            g_sense = s + 1u;
        } else {
            while (g_sense == s) { }
        }
        __threadfence();
    }
    __syncthreads();
}

__device__ __forceinline__ float tf32r(float x){
    uint32_t u; asm("cvt.rna.tf32.f32 %0, %1;" : "=r"(u) : "f"(x));
    return __uint_as_float(u);
}
__device__ __forceinline__ float fsigmoid(float x){ return 1.0f/(1.0f + __expf(-x)); }
__device__ __forceinline__ float ftanh(float x){ return 1.0f - 2.0f/(__expf(2.0f*x) + 1.0f); }

__device__ __forceinline__ void mma8(float (&d)[4], const uint32_t (&a)[4], const uint32_t (&b)[2]){
    asm volatile("mma.sync.aligned.m16n8k8.row.col.f32.tf32.tf32.f32 "
        "{%0,%1,%2,%3}, {%4,%5,%6,%7}, {%8,%9}, {%0,%1,%2,%3};"
        : "+f"(d[0]),"+f"(d[1]),"+f"(d[2]),"+f"(d[3])
        : "r"(a[0]),"r"(a[1]),"r"(a[2]),"r"(a[3]), "r"(b[0]),"r"(b[1]));
}

__device__ __forceinline__ void mma_tile(const float (*As)[36], const float (*Bs)[72],
                                         int wm, int wn, int g, int t4, float (&d)[2][2][4])
{
    #pragma unroll
    for (int ks = 0; ks < 4; ks++){
        const int k8 = ks*8;
        uint32_t a[2][4], b[2][2];
        #pragma unroll
        for (int mi = 0; mi < 2; mi++){
            const int mr = wm*32 + mi*16 + g;
            a[mi][0] = __float_as_uint(As[mr  ][k8+t4  ]);
            a[mi][1] = __float_as_uint(As[mr+8][k8+t4  ]);
            a[mi][2] = __float_as_uint(As[mr  ][k8+t4+4]);
            a[mi][3] = __float_as_uint(As[mr+8][k8+t4+4]);
        }
        #pragma unroll
        for (int ni = 0; ni < 2; ni++){
            const int nc = wn*16 + ni*8 + g;
            b[ni][0] = __float_as_uint(Bs[k8+t4  ][nc]);
            b[ni][1] = __float_as_uint(Bs[k8+t4+4][nc]);
        }
        #pragma unroll
        for (int mi = 0; mi < 2; mi++)
            #pragma unroll
            for (int ni = 0; ni < 2; ni++)
                mma8(d[mi][ni], a[mi], b[ni]);
    }
}

__device__ __forceinline__ void epi_store(float* Out, int ld, int m0, int n0,
                                          int wm, int wn, int g, int t4, float (&d)[2][2][4])
{
    #pragma unroll
    for (int mi = 0; mi < 2; mi++){
        const int r0 = m0 + wm*32 + mi*16 + g;
        #pragma unroll
        for (int ni = 0; ni < 2; ni++){
            const int c = n0 + wn*16 + ni*8 + t4*2;
            *(float2*)&Out[(size_t)r0*ld + c]     = make_float2(d[mi][ni][0], d[mi][ni][1]);
            *(float2*)&Out[(size_t)(r0+8)*ld + c] = make_float2(d[mi][ni][2], d[mi][ni][3]);
        }
    }
}

// ---- setup kernels ----
__global__ __launch_bounds__(256) void k_cvt4(const float* __restrict__ in,
                                              float* __restrict__ out, int n4)
{
    int i = blockIdx.x*256 + threadIdx.x;
    if (i >= n4) return;
    float4 v = *(const float4*)&in[i*4];
    v.x = tf32r(v.x); v.y = tf32r(v.y); v.z = tf32r(v.z); v.w = tf32r(v.w);
    *(float4*)&out[i*4] = v;
}

__global__ __launch_bounds__(256) void k_transpose(const float* __restrict__ W, int K,
                                                   float* __restrict__ WT)
{
    __shared__ float tile[32][33];
    const int j0 = blockIdx.x*32, k0 = blockIdx.y*32;
    const int r = threadIdx.x >> 3, c4 = (threadIdx.x & 7)*4;
    float4 v = *(const float4*)&W[(size_t)(j0+r)*K + k0 + c4];
    tile[r][c4+0]=v.x; tile[r][c4+1]=v.y; tile[r][c4+2]=v.z; tile[r][c4+3]=v.w;
    __syncthreads();
    float4 o = make_float4(tf32r(tile[c4+0][r]), tf32r(tile[c4+1][r]),
                           tf32r(tile[c4+2][r]), tf32r(tile[c4+3][r]));
    *(float4*)&WT[(size_t)(k0+r)*JC + j0 + c4] = o;
}

// ==================== THE persistent kernel ====================
__global__ __launch_bounds__(256, 2) void k_main(const float* __restrict__ data,
                                                 const float* __restrict__ b1,
                                                 const float* __restrict__ b2,
                                                 const float* __restrict__ bih,
                                                 const float* __restrict__ bhh,
                                                 float* __restrict__ out)
{
    __shared__ float As[2][64][36];
    __shared__ float Bs[2][32][72];
    const int tid = threadIdx.x;
    const int b   = blockIdx.x;
    const int lane = tid & 31, warp = tid >> 5;
    const int wm = warp >> 2, wn = warp & 3;
    const int g = lane >> 2, t4 = lane & 3;
    const int am = tid >> 2, akq = (tid & 3)*8;
    const int bk = tid >> 3, bnq = (tid & 7)*8;

    // zero initial state
    {
        const int e0 = b*(BATCH*LAT/NB) + tid*2;
        g_S0[e0] = 0.0f; g_S0[e0+1] = 0.0f;
    }
    gridbar();

    for (int t = 0; t < L_SEQ; t++){
        float* Sr = (t & 1) ? g_S1 : g_S0;
        float* Sw = (t & 1) ? g_S0 : g_S1;
        const int J = (t == L_SEQ-1) ? HID : LAT;
        const float* base = Sr;

        for (int s = 0; s < 3; s++){
            // ---------- phase A: mlp1 partials, tiles (16 n, 4 m, 4 z) ----------
            {
                const int n0 = (b & 15)*64, m0 = ((b>>4)&3)*64, z = b>>6;
                const int kb = z*128;
                float d[2][2][4];
                #pragma unroll
                for (int mi=0;mi<2;mi++) for (int ni=0;ni<2;ni++) for (int q=0;q<4;q++) d[mi][ni][q]=0.f;

                float ra[8]; float4 rb0, rb1;
                auto ldg = [&](int kt){
                    const float* pa = &base[(size_t)(m0+am)*LAT + kb + kt*32 + akq];
                    float4 v0 = *(const float4*)pa, v1 = *(const float4*)(pa+4);
                    ra[0]=tf32r(v0.x); ra[1]=tf32r(v0.y); ra[2]=tf32r(v0.z); ra[3]=tf32r(v0.w);
                    ra[4]=tf32r(v1.x); ra[5]=tf32r(v1.y); ra[6]=tf32r(v1.z); ra[7]=tf32r(v1.w);
                    const float* pb = &g_W1c[(size_t)(kb + kt*32 + bk)*HODE + n0 + bnq];
                    rb0 = *(const float4*)pb; rb1 = *(const float4*)(pb+4);
                };
                auto sts = [&](int c){
                    *(float4*)&As[c][am][akq]   = make_float4(ra[0],ra[1],ra[2],ra[3]);
                    *(float4*)&As[c][am][akq+4] = make_float4(ra[4],ra[5],ra[6],ra[7]);
                    *(float4*)&Bs[c][bk][bnq] = rb0; *(float4*)&Bs[c][bk][bnq+4] = rb1;
                };
                ldg(0); sts(0); __syncthreads();
                for (int kt = 0; kt < 4; kt++){
                    const int c = kt & 1;
                    if (kt < 3) ldg(kt+1);
                    mma_tile(As[c], Bs[c], wm, wn, g, t4, d);
                    if (kt < 3) sts(c^1);
                    __syncthreads();
                }
                epi_store(g_P[z], HODE, m0, n0, wm, wn, g, t4, d);
            }
            gridbar();

            // ---------- phase B: mlp2 partials, tiles (8 n, 4 m, 8 z) ----------
            {
                const int n0 = (b & 7)*64, m0 = ((b>>3)&3)*64, z = b>>5;
                const int kb = z*128;
                float d[2][2][4];
                #pragma unroll
                for (int mi=0;mi<2;mi++) for (int ni=0;ni<2;ni++) for (int q=0;q<4;q++) d[mi][ni][q]=0.f;

                float ra[8]; float4 rb0, rb1;
                auto ldg = [&](int kt){
                    const size_t off = (size_t)(m0+am)*HODE + kb + kt*32 + akq;
                    #pragma unroll
                    for (int hv = 0; hv < 2; hv++){
                        float4 p0 = *(const float4*)&g_P[0][off + hv*4];
                        float4 p1 = *(const float4*)&g_P[1][off + hv*4];
                        float4 p2 = *(const float4*)&g_P[2][off + hv*4];
                        float4 p3 = *(const float4*)&g_P[3][off + hv*4];
                        float4 cc = *(const float4*)&b1[kb + kt*32 + akq + hv*4];
                        ra[hv*4+0] = tf32r(ftanh(p0.x+p1.x+p2.x+p3.x+cc.x));
                        ra[hv*4+1] = tf32r(ftanh(p0.y+p1.y+p2.y+p3.y+cc.y));
                        ra[hv*4+2] = tf32r(ftanh(p0.z+p1.z+p2.z+p3.z+cc.z));
                        ra[hv*4+3] = tf32r(ftanh(p0.w+p1.w+p2.w+p3.w+cc.w));
                    }
                    const float* pb = &g_W2c[(size_t)(kb + kt*32 + bk)*LAT + n0 + bnq];
                    rb0 = *(const float4*)pb; rb1 = *(const float4*)(pb+4);
                };
                auto sts = [&](int c){
                    *(float4*)&As[c][am][akq]   = make_float4(ra[0],ra[1],ra[2],ra[3]);
                    *(float4*)&As[c][am][akq+4] = make_float4(ra[4],ra[5],ra[6],ra[7]);
                    *(float4*)&Bs[c][bk][bnq] = rb0; *(float4*)&Bs[c][bk][bnq+4] = rb1;
                };
                ldg(0); sts(0); __syncthreads();
                for (int kt = 0; kt < 4; kt++){
                    const int c = kt & 1;
                    if (kt < 3) ldg(kt+1);
                    mma_tile(As[c], Bs[c], wm, wn, g, t4, d);
                    if (kt < 3) sts(c^1);
                    __syncthreads();
                }
                epi_store(g_Q[z], LAT, m0, n0, wm, wn, g, t4, d);
            }
            gridbar();

            // ---------- phase C: euler combine (1 float2 per thread) ----------
            {
                const int e = (b*256 + tid)*2;
                const int m = e / LAT, n = e % LAT;
                const float h = data[(size_t)(t*BATCH + m)*DSTRIDE + DIN] * (1.0f/3.0f);
                float2 bb = *(const float2*)&base[e];
                float2 cc = *(const float2*)&b2[n];
                float sx = cc.x, sy = cc.y;
                #pragma unroll
                for (int z = 0; z < 8; z++){
                    float2 q = *(const float2*)&g_Q[z][e];
                    sx += q.x; sy += q.y;
                }
                *(float2*)&g_Y[e] = make_float2(bb.x + sx*h, bb.y + sy*h);
            }
            gridbar();
            base = g_Y;
        }

        // ---------- phase D: GRU gate-major partials ----------
        {
            const int CT = 3*J/64;
            const int ntiles = CT*4*3;
            for (int tile = b; tile < ntiles; tile += NB){
                const int ct = tile % CT;
                const int m0 = ((tile / CT) & 3)*64;
                const int z  = tile / (CT*4);
                const int c0 = ct*64;
                const int NC3 = 3*J;
                const int gate = c0 / J, j0 = c0 - gate*J;
                const int wcol = gate*1024 + j0;
                const int KT = (z == 0) ? 8 : 16;
                const float* WT = (z == 0) ? g_WihTc : g_WhhTc;
                const int krow0 = (z == 2) ? 512 : 0;

                float d[2][2][4];
                #pragma unroll
                for (int mi=0;mi<2;mi++) for (int ni=0;ni<2;ni++) for (int q=0;q<4;q++) d[mi][ni][q]=0.f;

                float ra[8]; float4 rb0, rb1;
                auto ldg = [&](int kt){
                    if (z == 0){
                        const float* pa = &data[(size_t)(t*BATCH + m0 + am)*DSTRIDE + kt*32 + akq];
                        #pragma unroll
                        for (int q = 0; q < 8; q++) ra[q] = tf32r(pa[q]);
                    } else {
                        const float* src = (z == 1) ? g_Y : Sr;
                        const float* pa = &src[(size_t)(m0+am)*LAT + kt*32 + akq];
                        float4 v0 = *(const float4*)pa, v1 = *(const float4*)(pa+4);
                        ra[0]=tf32r(v0.x); ra[1]=tf32r(v0.y); ra[2]=tf32r(v0.z); ra[3]=tf32r(v0.w);
                        ra[4]=tf32r(v1.x); ra[5]=tf32r(v1.y); ra[6]=tf32r(v1.z); ra[7]=tf32r(v1.w);
                    }
                    const float* pb = &WT[(size_t)(krow0 + kt*32 + bk)*JC + wcol + bnq];
                    rb0 = *(const float4*)pb; rb1 = *(const float4*)(pb+4);
                };
                auto sts = [&](int c){
                    *(float4*)&As[c][am][akq]   = make_float4(ra[0],ra[1],ra[2],ra[3]);
                    *(float4*)&As[c][am][akq+4] = make_float4(ra[4],ra[5],ra[6],ra[7]);
                    *(float4*)&Bs[c][bk][bnq] = rb0; *(float4*)&Bs[c][bk][bnq+4] = rb1;
                };
                ldg(0); sts(0); __syncthreads();
                for (int kt = 0; kt < KT; kt++){
                    const int c = kt & 1;
                    if (kt < KT-1) ldg(kt+1);
                    mma_tile(As[c], Bs[c], wm, wn, g, t4, d);
                    if (kt < KT-1) sts(c^1);
                    __syncthreads();
                }
                epi_store(g_Gp[z], NC3, m0, c0, wm, wn, g, t4, d);
            }
        }
        gridbar();

        // ---------- phase E: gates ----------
        {
            const int tot = BATCH*J/2;
            const int NC3 = 3*J;
            const bool last = (t == L_SEQ-1);
            for (int idx = b*256 + tid; idx < tot; idx += NB*256){
                const int e = idx*2;
                const int i = e / J, j = e - (e/J)*J;
                const size_t gb = (size_t)i*NC3;
                float2 r0 = *(const float2*)&g_Gp[0][gb + j];
                float2 r1 = *(const float2*)&g_Gp[1][gb + j];
                float2 r2 = *(const float2*)&g_Gp[2][gb + j];
                float2 z0 = *(const float2*)&g_Gp[0][gb + J + j];
                float2 z1 = *(const float2*)&g_Gp[1][gb + J + j];
                float2 z2 = *(const float2*)&g_Gp[2][gb + J + j];
                float2 x0 = *(const float2*)&g_Gp[0][gb + 2*J + j];
                float2 h1 = *(const float2*)&g_Gp[1][gb + 2*J + j];
                float2 h2 = *(const float2*)&g_Gp[2][gb + 2*J + j];
                float rs[2] = { r0.x+r1.x+r2.x, r0.y+r1.y+r2.y };
                float zs[2] = { z0.x+z1.x+z2.x, z0.y+z1.y+z2.y };
                float xs[2] = { x0.x, x0.y };
                float hs[2] = { h1.x+h2.x, h1.y+h2.y };
                #pragma unroll
                for (int q = 0; q < 2; q++){
                    const int jj = j + q;
                    float rg = fsigmoid(rs[q] + bih[jj] + bhh[jj]);
                    float zg = fsigmoid(zs[q] + bih[HID+jj] + bhh[HID+jj]);
                    float ng = ftanh((xs[q] + bih[2*HID+jj]) + rg*(hs[q] + bhh[2*HID+jj]));
                    float hv = (jj < LAT) ? g_Y[(size_t)i*LAT + jj]
                                          : Sr[(size_t)i*LAT + jj - LAT];
                    float v = (1.0f - zg)*ng + zg*hv;
                    if (jj < LAT){
                        out[(size_t)(t*BATCH + i)*LAT + jj] = v;
                        Sw[(size_t)i*LAT + jj] = v;
                    }
                    if (last) out[OUT2_OFF + (size_t)i*HID + jj] = v;
                }
            }
        }
        gridbar();
    }
}

extern "C" void kernel_launch(void* const* d_in, const int* in_sizes, int n_in,
                              void* d_out, int out_size)
{
    const float* data = (const float*)d_in[0];
    const float* w1   = (const float*)d_in[1];
    const float* b1   = (const float*)d_in[2];
    const float* w2   = (const float*)d_in[3];
    const float* b2   = (const float*)d_in[4];
    const float* wih  = (const float*)d_in[5];
    const float* bih  = (const float*)d_in[6];
    const float* whh  = (const float*)d_in[7];
    const float* bhh  = (const float*)d_in[8];
    float* out = (float*)d_out;

    float *W1c, *W2c, *WihT, *WhhT;
    cudaGetSymbolAddress((void**)&W1c, g_W1c);
    cudaGetSymbolAddress((void**)&W2c, g_W2c);
    cudaGetSymbolAddress((void**)&WihT, g_WihTc);
    cudaGetSymbolAddress((void**)&WhhT, g_WhhTc);

    k_cvt4<<<(LAT*HODE/4 + 255)/256, 256>>>(w1, W1c, LAT*HODE/4);
    k_cvt4<<<(HODE*LAT/4 + 255)/256, 256>>>(w2, W2c, HODE*LAT/4);
    k_transpose<<<dim3(JC/32, DIN/32), 256>>>(wih, DIN, WihT);
    k_transpose<<<dim3(JC/32, HID/32), 256>>>(whh, HID, WhhT);

    k_main<<<NB, 256>>>(data, b1, b2, bih, bhh, out);

    (void)in_sizes; (void)n_in; (void)out_size;
}

// round 12
// speedup vs baseline: 1.0569x; 1.0569x over previous
#include <cuda_runtime.h>
#include <cstdint>

#define L_SEQ  50
#define BATCH  256
#define DIN    256
#define LAT    512
#define HODE   1024
#define HID    1024
#define DSTRIDE 257
#define JC     3072
#define OUT2_OFF (L_SEQ*BATCH*LAT)
#define NB     256

// ---- persistent scratch ----
__device__ float g_S0[BATCH*LAT];
__device__ float g_S1[BATCH*LAT];
__device__ float g_Y [BATCH*LAT];
__device__ float g_P [4][BATCH*HODE];     // mlp1 split-K partials
__device__ float g_Q [8][BATCH*LAT];      // mlp2 split-K partials
__device__ float g_Gp[5][BATCH*JC];       // gru partials per K-slice, gate-major
__device__ float g_W1c [LAT*HODE];        // tf32-rounded weights (immutable -> L1-cached)
__device__ float g_W2c [HODE*LAT];
__device__ float g_WihTc[DIN*JC];
__device__ float g_WhhTc[HID*JC];

// ---- flush-free, launch-idempotent grid barrier (sense-reversal, acq/rel) ----
__device__ unsigned g_cnt = 0;
__device__ unsigned g_sense = 0;

__device__ __forceinline__ void gridbar(){
    __syncthreads();
    if (threadIdx.x == 0){
        unsigned s;
        asm volatile("ld.acquire.gpu.u32 %0, [%1];" : "=r"(s) : "l"(&g_sense) : "memory");
        unsigned old;
        asm volatile("atom.add.acq_rel.gpu.u32 %0, [%1], 1;"
                     : "=r"(old) : "l"(&g_cnt) : "memory");
        if (old == NB-1u){
            asm volatile("st.relaxed.gpu.u32 [%0], %1;" :: "l"(&g_cnt), "r"(0u) : "memory");
            asm volatile("st.release.gpu.u32 [%0], %1;" :: "l"(&g_sense), "r"(s+1u) : "memory");
        } else {
            unsigned v;
            do {
                asm volatile("ld.acquire.gpu.u32 %0, [%1];" : "=r"(v) : "l"(&g_sense) : "memory");
            } while (v == s);
        }
    }
    __syncthreads();
}

__device__ __forceinline__ float tf32r(float x){
    uint32_t u; asm("cvt.rna.tf32.f32 %0, %1;" : "=r"(u) : "f"(x));
    return __uint_as_float(u);
}
__device__ __forceinline__ float fsigmoid(float x){ return 1.0f/(1.0f + __expf(-x)); }
__device__ __forceinline__ float ftanh(float x){ return 1.0f - 2.0f/(__expf(2.0f*x) + 1.0f); }

__device__ __forceinline__ void mma8(float (&d)[4], const uint32_t (&a)[4], const uint32_t (&b)[2]){
    asm volatile("mma.sync.aligned.m16n8k8.row.col.f32.tf32.tf32.f32 "
        "{%0,%1,%2,%3}, {%4,%5,%6,%7}, {%8,%9}, {%0,%1,%2,%3};"
        : "+f"(d[0]),"+f"(d[1]),"+f"(d[2]),"+f"(d[3])
        : "r"(a[0]),"r"(a[1]),"r"(a[2]),"r"(a[3]), "r"(b[0]),"r"(b[1]));
}

// A stored k-permuted: col = (k&3)*8 + (k>>2). Load 8 LDS.128 -> all fragments.
__device__ __forceinline__ void load_afrag(const float (*As)[36], int wm, int g, int t4,
                                           float (&Ar)[4][8])
{
    #pragma unroll
    for (int rr = 0; rr < 4; rr++){
        const int row = wm*32 + rr*8 + g;
        float4 h0 = *(const float4*)&As[row][t4*8];
        float4 h1 = *(const float4*)&As[row][t4*8+4];
        Ar[rr][0]=h0.x; Ar[rr][1]=h0.y; Ar[rr][2]=h0.z; Ar[rr][3]=h0.w;
        Ar[rr][4]=h1.x; Ar[rr][5]=h1.y; Ar[rr][6]=h1.z; Ar[rr][7]=h1.w;
    }
}

__device__ __forceinline__ void mma_tile_perm(const float (&Ar)[4][8], const float (*Bs)[72],
                                              int wn, int g, int t4, float (&d)[2][2][4])
{
    #pragma unroll
    for (int ks = 0; ks < 4; ks++){
        const int k8 = ks*8;
        uint32_t b[2][2];
        #pragma unroll
        for (int ni = 0; ni < 2; ni++){
            const int nc = wn*16 + ni*8 + g;
            b[ni][0] = __float_as_uint(Bs[k8+t4  ][nc]);
            b[ni][1] = __float_as_uint(Bs[k8+t4+4][nc]);
        }
        #pragma unroll
        for (int mi = 0; mi < 2; mi++){
            uint32_t a[4] = { __float_as_uint(Ar[2*mi  ][2*ks  ]),
                              __float_as_uint(Ar[2*mi+1][2*ks  ]),
                              __float_as_uint(Ar[2*mi  ][2*ks+1]),
                              __float_as_uint(Ar[2*mi+1][2*ks+1]) };
            #pragma unroll
            for (int ni = 0; ni < 2; ni++)
                mma8(d[mi][ni], a, b[ni]);
        }
    }
}

// stage 8 values (global-k contiguous at local base q*8) into permuted row am
__device__ __forceinline__ void stageA(float (*As)[36], int am, int q, const float* v8){
    #pragma unroll
    for (int j = 0; j < 8; j++)
        As[am][(j&3)*8 + 2*q + (j>>2)] = v8[j];
}

__device__ __forceinline__ void epi_store_cg(float* Out, int ld, int m0, int n0,
                                             int wm, int wn, int g, int t4, float (&d)[2][2][4])
{
    #pragma unroll
    for (int mi = 0; mi < 2; mi++){
        const int r0 = m0 + wm*32 + mi*16 + g;
        #pragma unroll
        for (int ni = 0; ni < 2; ni++){
            const int c = n0 + wn*16 + ni*8 + t4*2;
            __stcg((float2*)&Out[(size_t)r0*ld + c],     make_float2(d[mi][ni][0], d[mi][ni][1]));
            __stcg((float2*)&Out[(size_t)(r0+8)*ld + c], make_float2(d[mi][ni][2], d[mi][ni][3]));
        }
    }
}

// ---- setup kernels ----
__global__ __launch_bounds__(256) void k_cvt4(const float* __restrict__ in,
                                              float* __restrict__ out, int n4)
{
    int i = blockIdx.x*256 + threadIdx.x;
    if (i >= n4) return;
    float4 v = *(const float4*)&in[i*4];
    v.x = tf32r(v.x); v.y = tf32r(v.y); v.z = tf32r(v.z); v.w = tf32r(v.w);
    *(float4*)&out[i*4] = v;
}

__global__ __launch_bounds__(256) void k_transpose(const float* __restrict__ W, int K,
                                                   float* __restrict__ WT)
{
    __shared__ float tile[32][33];
    const int j0 = blockIdx.x*32, k0 = blockIdx.y*32;
    const int r = threadIdx.x >> 3, c4 = (threadIdx.x & 7)*4;
    float4 v = *(const float4*)&W[(size_t)(j0+r)*K + k0 + c4];
    tile[r][c4+0]=v.x; tile[r][c4+1]=v.y; tile[r][c4+2]=v.z; tile[r][c4+3]=v.w;
    __syncthreads();
    float4 o = make_float4(tf32r(tile[c4+0][r]), tf32r(tile[c4+1][r]),
                           tf32r(tile[c4+2][r]), tf32r(tile[c4+3][r]));
    *(float4*)&WT[(size_t)(k0+r)*JC + j0 + c4] = o;
}

// ==================== THE persistent kernel ====================
__global__ __launch_bounds__(256, 2) void k_main(const float* __restrict__ data,
                                                 const float* __restrict__ b1,
                                                 const float* __restrict__ b2,
                                                 const float* __restrict__ bih,
                                                 const float* __restrict__ bhh,
                                                 float* __restrict__ out)
{
    __shared__ float As[2][64][36];
    __shared__ float Bs[2][32][72];
    const int tid = threadIdx.x;
    const int b   = blockIdx.x;
    const int lane = tid & 31, warp = tid >> 5;
    const int wm = warp >> 2, wn = warp & 3;
    const int g = lane >> 2, t4 = lane & 3;
    const int am = tid >> 2, q = tid & 3, q8 = q*8;    // A staging
    const int bk = tid >> 3, bnq = (tid & 7)*8;        // B staging

    // zero initial state
    {
        const int e0 = b*(BATCH*LAT/NB) + tid*2;
        __stcg((float2*)&g_S0[e0], make_float2(0.f, 0.f));
    }
    gridbar();

    for (int t = 0; t < L_SEQ; t++){
        float* Sr = (t & 1) ? g_S1 : g_S0;
        float* Sw = (t & 1) ? g_S0 : g_S1;
        const int J = (t == L_SEQ-1) ? HID : LAT;
        const float* base = Sr;

        for (int s = 0; s < 3; s++){
            // ---------- phase A: mlp1 partials, tiles (16 n, 4 m, 4 z), KT=4 ----------
            {
                const int n0 = (b & 15)*64, m0 = ((b>>4)&3)*64, z = b>>6;
                const int kb = z*128;
                float d[2][2][4];
                #pragma unroll
                for (int mi=0;mi<2;mi++) for (int ni=0;ni<2;ni++) for (int p=0;p<4;p++) d[mi][ni][p]=0.f;

                float va[8]; float4 rb0, rb1;
                auto ldg = [&](int kt){
                    const float* pa = &base[(size_t)(m0+am)*LAT + kb + kt*32 + q8];
                    float4 v0 = __ldcg((const float4*)pa);
                    float4 v1 = __ldcg((const float4*)(pa+4));
                    va[0]=tf32r(v0.x); va[1]=tf32r(v0.y); va[2]=tf32r(v0.z); va[3]=tf32r(v0.w);
                    va[4]=tf32r(v1.x); va[5]=tf32r(v1.y); va[6]=tf32r(v1.z); va[7]=tf32r(v1.w);
                    const float* pb = &g_W1c[(size_t)(kb + kt*32 + bk)*HODE + n0 + bnq];
                    rb0 = *(const float4*)pb; rb1 = *(const float4*)(pb+4);
                };
                auto sts = [&](int c){
                    stageA(As[c], am, q, va);
                    *(float4*)&Bs[c][bk][bnq] = rb0; *(float4*)&Bs[c][bk][bnq+4] = rb1;
                };
                ldg(0); sts(0); __syncthreads();
                for (int kt = 0; kt < 4; kt++){
                    const int c = kt & 1;
                    if (kt < 3) ldg(kt+1);
                    float Ar[4][8];
                    load_afrag(As[c], wm, g, t4, Ar);
                    mma_tile_perm(Ar, Bs[c], wn, g, t4, d);
                    if (kt < 3) sts(c^1);
                    __syncthreads();
                }
                epi_store_cg(g_P[z], HODE, m0, n0, wm, wn, g, t4, d);
            }
            gridbar();

            // ---------- phase B: mlp2 partials, tiles (8 n, 4 m, 8 z), KT=4 ----------
            {
                const int n0 = (b & 7)*64, m0 = ((b>>3)&3)*64, z = b>>5;
                const int kb = z*128;
                float d[2][2][4];
                #pragma unroll
                for (int mi=0;mi<2;mi++) for (int ni=0;ni<2;ni++) for (int p=0;p<4;p++) d[mi][ni][p]=0.f;

                float va[8]; float4 rb0, rb1;
                auto ldg = [&](int kt){
                    const size_t off = (size_t)(m0+am)*HODE + kb + kt*32 + q8;
                    float4 a0 = __ldcg((const float4*)&g_P[0][off]);
                    float4 a1 = __ldcg((const float4*)&g_P[1][off]);
                    float4 a2 = __ldcg((const float4*)&g_P[2][off]);
                    float4 a3 = __ldcg((const float4*)&g_P[3][off]);
                    float4 d0 = __ldcg((const float4*)&g_P[0][off+4]);
                    float4 d1 = __ldcg((const float4*)&g_P[1][off+4]);
                    float4 d2 = __ldcg((const float4*)&g_P[2][off+4]);
                    float4 d3 = __ldcg((const float4*)&g_P[3][off+4]);
                    float4 c0 = *(const float4*)&b1[kb + kt*32 + q8];
                    float4 c1 = *(const float4*)&b1[kb + kt*32 + q8 + 4];
                    va[0]=tf32r(ftanh(a0.x+a1.x+a2.x+a3.x+c0.x));
                    va[1]=tf32r(ftanh(a0.y+a1.y+a2.y+a3.y+c0.y));
                    va[2]=tf32r(ftanh(a0.z+a1.z+a2.z+a3.z+c0.z));
                    va[3]=tf32r(ftanh(a0.w+a1.w+a2.w+a3.w+c0.w));
                    va[4]=tf32r(ftanh(d0.x+d1.x+d2.x+d3.x+c1.x));
                    va[5]=tf32r(ftanh(d0.y+d1.y+d2.y+d3.y+c1.y));
                    va[6]=tf32r(ftanh(d0.z+d1.z+d2.z+d3.z+c1.z));
                    va[7]=tf32r(ftanh(d0.w+d1.w+d2.w+d3.w+c1.w));
                    const float* pb = &g_W2c[(size_t)(kb + kt*32 + bk)*LAT + n0 + bnq];
                    rb0 = *(const float4*)pb; rb1 = *(const float4*)(pb+4);
                };
                auto sts = [&](int c){
                    stageA(As[c], am, q, va);
                    *(float4*)&Bs[c][bk][bnq] = rb0; *(float4*)&Bs[c][bk][bnq+4] = rb1;
                };
                ldg(0); sts(0); __syncthreads();
                for (int kt = 0; kt < 4; kt++){
                    const int c = kt & 1;
                    if (kt < 3) ldg(kt+1);
                    float Ar[4][8];
                    load_afrag(As[c], wm, g, t4, Ar);
                    mma_tile_perm(Ar, Bs[c], wn, g, t4, d);
                    if (kt < 3) sts(c^1);
                    __syncthreads();
                }
                epi_store_cg(g_Q[z], LAT, m0, n0, wm, wn, g, t4, d);
            }
            gridbar();

            // ---------- phase C: euler combine ----------
            {
                const int e = (b*256 + tid)*2;
                const int m = e / LAT, n = e % LAT;
                const float h = data[(size_t)(t*BATCH + m)*DSTRIDE + DIN] * (1.0f/3.0f);
                float2 bb = __ldcg((const float2*)&base[e]);
                float2 cc = *(const float2*)&b2[n];
                float sx = cc.x, sy = cc.y;
                #pragma unroll
                for (int z = 0; z < 8; z++){
                    float2 qv = __ldcg((const float2*)&g_Q[z][e]);
                    sx += qv.x; sy += qv.y;
                }
                __stcg((float2*)&g_Y[e], make_float2(bb.x + sx*h, bb.y + sy*h));
            }
            gridbar();
            base = g_Y;
        }

        // ---------- phase D: GRU partials; 5 uniform K-slices of 256, KT=8 ----------
        {
            const int CT = 3*J/64;
            const int ntiles = CT*4*5;
            const int NC3 = 3*J;
            for (int tile = b; tile < ntiles; tile += NB){
                const int ct = tile % CT;
                const int m0 = ((tile / CT) & 3)*64;
                const int z  = tile / (CT*4);
                const int c0 = ct*64;
                const int gate = c0 / J, j0 = c0 - gate*J;
                const int wcol = gate*1024 + j0;
                const float* WT = (z == 0) ? g_WihTc : g_WhhTc;
                const int krow0 = (z == 0) ? 0 : (z-1)*256;
                const float* Asrc = (z <= 2) ? g_Y : Sr;       // z==0 unused
                const int kc0 = (z == 0) ? 0 : ((z == 1 || z == 3) ? 0 : 256);

                float d[2][2][4];
                #pragma unroll
                for (int mi=0;mi<2;mi++) for (int ni=0;ni<2;ni++) for (int p=0;p<4;p++) d[mi][ni][p]=0.f;

                float va[8]; float4 rb0, rb1;
                auto ldg = [&](int kt){
                    if (z == 0){
                        const float* pa = &data[(size_t)(t*BATCH + m0 + am)*DSTRIDE + kt*32 + q8];
                        #pragma unroll
                        for (int j = 0; j < 8; j++) va[j] = tf32r(pa[j]);
                    } else {
                        const float* pa = &Asrc[(size_t)(m0+am)*LAT + kc0 + kt*32 + q8];
                        float4 v0 = __ldcg((const float4*)pa);
                        float4 v1 = __ldcg((const float4*)(pa+4));
                        va[0]=tf32r(v0.x); va[1]=tf32r(v0.y); va[2]=tf32r(v0.z); va[3]=tf32r(v0.w);
                        va[4]=tf32r(v1.x); va[5]=tf32r(v1.y); va[6]=tf32r(v1.z); va[7]=tf32r(v1.w);
                    }
                    const float* pb = &WT[(size_t)(krow0 + kt*32 + bk)*JC + wcol + bnq];
                    rb0 = *(const float4*)pb; rb1 = *(const float4*)(pb+4);
                };
                auto sts = [&](int c){
                    stageA(As[c], am, q, va);
                    *(float4*)&Bs[c][bk][bnq] = rb0; *(float4*)&Bs[c][bk][bnq+4] = rb1;
                };
                ldg(0); sts(0); __syncthreads();
                for (int kt = 0; kt < 8; kt++){
                    const int c = kt & 1;
                    if (kt < 7) ldg(kt+1);
                    float Ar[4][8];
                    load_afrag(As[c], wm, g, t4, Ar);
                    mma_tile_perm(Ar, Bs[c], wn, g, t4, d);
                    if (kt < 7) sts(c^1);
                    __syncthreads();
                }
                epi_store_cg(g_Gp[z], NC3, m0, c0, wm, wn, g, t4, d);
                __syncthreads();
            }
        }
        gridbar();

        // ---------- phase E: gates ----------
        {
            const int tot = BATCH*J/2;
            const int NC3 = 3*J;
            const bool last = (t == L_SEQ-1);
            for (int idx = b*256 + tid; idx < tot; idx += NB*256){
                const int e = idx*2;
                const int i = e / J, j = e - (e/J)*J;
                const size_t gb = (size_t)i*NC3;
                float rs0=0.f, rs1=0.f, zs0=0.f, zs1=0.f, hs0=0.f, hs1=0.f;
                #pragma unroll
                for (int z = 1; z < 5; z++){
                    float2 rv = __ldcg((const float2*)&g_Gp[z][gb + j]);
                    float2 zv = __ldcg((const float2*)&g_Gp[z][gb + J + j]);
                    float2 hv = __ldcg((const float2*)&g_Gp[z][gb + 2*J + j]);
                    rs0 += rv.x; rs1 += rv.y;  zs0 += zv.x; zs1 += zv.y;
                    hs0 += hv.x; hs1 += hv.y;
                }
                {
                    float2 rv = __ldcg((const float2*)&g_Gp[0][gb + j]);
                    float2 zv = __ldcg((const float2*)&g_Gp[0][gb + J + j]);
                    rs0 += rv.x; rs1 += rv.y;  zs0 += zv.x; zs1 += zv.y;
                }
                float2 xv = __ldcg((const float2*)&g_Gp[0][gb + 2*J + j]);
                float rs[2] = { rs0, rs1 }, zs[2] = { zs0, zs1 };
                float xs[2] = { xv.x, xv.y }, hs[2] = { hs0, hs1 };
                #pragma unroll
                for (int p = 0; p < 2; p++){
                    const int jj = j + p;
                    float rg = fsigmoid(rs[p] + bih[jj] + bhh[jj]);
                    float zg = fsigmoid(zs[p] + bih[HID+jj] + bhh[HID+jj]);
                    float ng = ftanh((xs[p] + bih[2*HID+jj]) + rg*(hs[p] + bhh[2*HID+jj]));
                    float hv = (jj < LAT) ? __ldcg(&g_Y[(size_t)i*LAT + jj])
                                          : __ldcg(&Sr[(size_t)i*LAT + jj - LAT]);
                    float v = (1.0f - zg)*ng + zg*hv;
                    if (jj < LAT){
                        out[(size_t)(t*BATCH + i)*LAT + jj] = v;
                        __stcg(&Sw[(size_t)i*LAT + jj], v);
                    }
                    if (last) out[OUT2_OFF + (size_t)i*HID + jj] = v;
                }
            }
        }
        gridbar();
    }
}

extern "C" void kernel_launch(void* const* d_in, const int* in_sizes, int n_in,
                              void* d_out, int out_size)
{
    const float* data = (const float*)d_in[0];
    const float* w1   = (const float*)d_in[1];
    const float* b1   = (const float*)d_in[2];
    const float* w2   = (const float*)d_in[3];
    const float* b2   = (const float*)d_in[4];
    const float* wih  = (const float*)d_in[5];
    const float* bih  = (const float*)d_in[6];
    const float* whh  = (const float*)d_in[7];
    const float* bhh  = (const float*)d_in[8];
    float* out = (float*)d_out;

    float *W1c, *W2c, *WihT, *WhhT;
    cudaGetSymbolAddress((void**)&W1c, g_W1c);
    cudaGetSymbolAddress((void**)&W2c, g_W2c);
    cudaGetSymbolAddress((void**)&WihT, g_WihTc);
    cudaGetSymbolAddress((void**)&WhhT, g_WhhTc);

    k_cvt4<<<(LAT*HODE/4 + 255)/256, 256>>>(w1, W1c, LAT*HODE/4);
    k_cvt4<<<(HODE*LAT/4 + 255)/256, 256>>>(w2, W2c, HODE*LAT/4);
    k_transpose<<<dim3(JC/32, DIN/32), 256>>>(wih, DIN, WihT);
    k_transpose<<<dim3(JC/32, HID/32), 256>>>(whh, HID, WhhT);

    k_main<<<NB, 256>>>(data, b1, b2, bih, bhh, out);

    (void)in_sizes; (void)n_in; (void)out_size;
}